// round 2
// baseline (speedup 1.0000x reference)
#include <cuda_runtime.h>
#include <math.h>

// MoE FFN: x[N,D] -> router top-2 of E -> grouped expert FFN (D->H gelu H->D) -> combine.
// N=4096, D=1024, H=4096, E=8 for this problem (dims derived at runtime, caps below).

#define MAXE      16
#define CAP_ROWS  8192          // N * TOP_K
#define CAP_H     4096
#define CAP_D     1024

__device__ int   g_cnt[MAXE];
__device__ int   g_off[MAXE];
__device__ int   g_cur[MAXE];
__device__ int   g_rows[CAP_ROWS];     // grouped list: token*2 + slot
__device__ int   g_tki[CAP_ROWS];      // per (token,slot): expert id
__device__ float g_tkw[CAP_ROWS];      // per (token,slot): routing weight
__device__ float g_hidden[(size_t)CAP_ROWS * CAP_H];  // 128 MB scratch
__device__ float g_ybuf[(size_t)CAP_ROWS * CAP_D];    // 32 MB scratch

// ---------------------------------------------------------------- init
__global__ void init_kernel(int E) {
    if (threadIdx.x < E) g_cnt[threadIdx.x] = 0;
}

// ---------------------------------------------------------------- router
// one block (128 threads) per token: logits = x_row @ gate_w, top-2, renorm.
__global__ __launch_bounds__(128) void router_kernel(
    const float* __restrict__ x, const float* __restrict__ gw,
    int D, int E)
{
    int n = blockIdx.x;
    int t = threadIdx.x;
    float acc[MAXE];
    #pragma unroll
    for (int e = 0; e < MAXE; e++) acc[e] = 0.f;

    const float* xr = x + (size_t)n * D;
    for (int i = t; i < D; i += 128) {
        float xv = xr[i];
        const float* g = gw + (size_t)i * E;
        for (int e = 0; e < E; e++) acc[e] += xv * g[e];
    }
    // warp reduce each logit
    for (int e = 0; e < E; e++)
        for (int o = 16; o > 0; o >>= 1)
            acc[e] += __shfl_down_sync(0xffffffffu, acc[e], o);

    __shared__ float sred[4][MAXE];
    int warp = t >> 5, lane = t & 31;
    if (lane == 0)
        for (int e = 0; e < E; e++) sred[warp][e] = acc[e];
    __syncthreads();

    if (t == 0) {
        float l[MAXE];
        for (int e = 0; e < E; e++)
            l[e] = sred[0][e] + sred[1][e] + sred[2][e] + sred[3][e];
        // top-2 (jax top_k: descending, ties -> lower index)
        int i0 = 0;
        for (int e = 1; e < E; e++) if (l[e] > l[i0]) i0 = e;
        int i1 = -1;
        for (int e = 0; e < E; e++) {
            if (e == i0) continue;
            if (i1 < 0 || l[e] > l[i1]) i1 = e;
        }
        // renormalized softmax over top-2 (full-softmax Z cancels)
        float e1 = expf(l[i1] - l[i0]);
        float s  = 1.0f + e1;
        g_tki[n * 2 + 0] = i0;  g_tkw[n * 2 + 0] = 1.0f / s;
        g_tki[n * 2 + 1] = i1;  g_tkw[n * 2 + 1] = e1 / s;
        atomicAdd(&g_cnt[i0], 1);
        atomicAdd(&g_cnt[i1], 1);
    }
}

// ---------------------------------------------------------------- scan
__global__ void scan_kernel(int E) {
    if (threadIdx.x == 0) {
        int off = 0;
        for (int e = 0; e < E; e++) {
            g_off[e] = off; g_cur[e] = off; off += g_cnt[e];
        }
    }
}

// ---------------------------------------------------------------- scatter
__global__ void scatter_kernel(int N) {
    int n = blockIdx.x * blockDim.x + threadIdx.x;
    if (n >= N) return;
    #pragma unroll
    for (int k = 0; k < 2; k++) {
        int e = g_tki[n * 2 + k];
        int p = atomicAdd(&g_cur[e], 1);
        g_rows[p] = n * 2 + k;
    }
}

// ---------------------------------------------------------------- grouped GEMM
// STAGE 1: hidden[p, :] = gelu( x[token(p), :] @ w1[e] + b1[e] )   K=D, NC=H
// STAGE 2: ybuf[rows(p), :] =  hidden[p, :] @ w2[e] + b2[e]        K=H, NC=D
// 128x128x16 tile, 256 threads, 8x8 per thread. M ragged per expert; NC,K
// are multiples of 128/16 for this problem.
template<int STAGE>
__global__ __launch_bounds__(256) void gemm_kernel(
    const float* __restrict__ Xin,     // x (stage1) / unused (stage2)
    const float* __restrict__ Ball,    // w1 or w2: [E, K, NC]
    const float* __restrict__ biasall, // [E, NC]
    int K, int NC)
{
    constexpr int BM = 128, BN = 128, BK = 16;
    int e   = blockIdx.z;
    int cnt = g_cnt[e];
    int m0  = blockIdx.y * BM;
    if (m0 >= cnt) return;
    int off = g_off[e];
    int n0  = blockIdx.x * BN;
    const float* B    = Ball    + (size_t)e * K * NC + n0;
    const float* bias = biasall + (size_t)e * NC + n0;

    __shared__ float As[BK][BM];
    __shared__ float Bs[BK][BN];

    int tid = threadIdx.x;

    // A-load mapping: 2 float4 per thread along K
    const float* arow[2];
    int am[2], ak4[2];
    bool avalid[2];
    #pragma unroll
    for (int it = 0; it < 2; it++) {
        int idx = tid + it * 256;
        int m = idx >> 2, k4 = idx & 3;
        am[it] = m; ak4[it] = k4;
        int mg = m0 + m;
        avalid[it] = (mg < cnt);
        int p = off + (avalid[it] ? mg : 0);
        if (STAGE == 1) {
            int token = g_rows[p] >> 1;
            arow[it] = Xin + (size_t)token * K;
        } else {
            arow[it] = &g_hidden[(size_t)p * K];
        }
    }

    int tm = (tid >> 4) << 3;
    int tn = (tid & 15) << 3;

    float acc[8][8];
    #pragma unroll
    for (int i = 0; i < 8; i++)
        #pragma unroll
        for (int j = 0; j < 8; j++) acc[i][j] = 0.f;

    for (int k0 = 0; k0 < K; k0 += BK) {
        #pragma unroll
        for (int it = 0; it < 2; it++) {
            float4 v = make_float4(0.f, 0.f, 0.f, 0.f);
            if (avalid[it])
                v = *(const float4*)(arow[it] + k0 + ak4[it] * 4);
            As[ak4[it] * 4 + 0][am[it]] = v.x;
            As[ak4[it] * 4 + 1][am[it]] = v.y;
            As[ak4[it] * 4 + 2][am[it]] = v.z;
            As[ak4[it] * 4 + 3][am[it]] = v.w;
        }
        #pragma unroll
        for (int it = 0; it < 2; it++) {
            int idx = tid + it * 256;
            int kk = idx >> 5, nn = (idx & 31) << 2;
            *(float4*)&Bs[kk][nn] =
                *(const float4*)(B + (size_t)(k0 + kk) * NC + nn);
        }
        __syncthreads();

        #pragma unroll
        for (int kk = 0; kk < BK; kk++) {
            float a[8], b[8];
            *(float4*)&a[0] = *(const float4*)&As[kk][tm];
            *(float4*)&a[4] = *(const float4*)&As[kk][tm + 4];
            *(float4*)&b[0] = *(const float4*)&Bs[kk][tn];
            *(float4*)&b[4] = *(const float4*)&Bs[kk][tn + 4];
            #pragma unroll
            for (int i = 0; i < 8; i++)
                #pragma unroll
                for (int j = 0; j < 8; j++)
                    acc[i][j] += a[i] * b[j];
        }
        __syncthreads();
    }

    float bv[8];
    *(float4*)&bv[0] = *(const float4*)&bias[tn];
    *(float4*)&bv[4] = *(const float4*)&bias[tn + 4];

    #pragma unroll
    for (int i = 0; i < 8; i++) {
        int mg = m0 + tm + i;
        if (mg >= cnt) continue;
        int p = off + mg;
        float* dst;
        if (STAGE == 1) {
            dst = &g_hidden[(size_t)p * NC + n0 + tn];
        } else {
            int dr = g_rows[p];
            dst = &g_ybuf[(size_t)dr * NC + n0 + tn];
        }
        float o[8];
        #pragma unroll
        for (int j = 0; j < 8; j++) {
            float v = acc[i][j] + bv[j];
            if (STAGE == 1)
                v = 0.5f * v * (1.0f + erff(v * 0.70710678118654752f));
            o[j] = v;
        }
        *(float4*)dst       = *(float4*)&o[0];
        *(float4*)(dst + 4) = *(float4*)&o[4];
    }
}

// ---------------------------------------------------------------- combine
__global__ void combine_kernel(float* __restrict__ out, int N, int Dq) {
    int id = blockIdx.x * blockDim.x + threadIdx.x;
    if (id >= N * Dq) return;
    int n = id / Dq, d4 = id % Dq;
    float w0 = g_tkw[n * 2 + 0];
    float w1 = g_tkw[n * 2 + 1];
    const float4* y0 = (const float4*)&g_ybuf[(size_t)(n * 2 + 0) * Dq * 4];
    const float4* y1 = (const float4*)&g_ybuf[(size_t)(n * 2 + 1) * Dq * 4];
    float4 a = y0[d4], b = y1[d4];
    float4 r;
    r.x = w0 * a.x + w1 * b.x;
    r.y = w0 * a.y + w1 * b.y;
    r.z = w0 * a.z + w1 * b.z;
    r.w = w0 * a.w + w1 * b.w;
    ((float4*)out)[id] = r;
}

// ---------------------------------------------------------------- launch
extern "C" void kernel_launch(void* const* d_in, const int* in_sizes, int n_in,
                              void* d_out, int out_size) {
    const float* x  = (const float*)d_in[0];   // [B,T,D]
    const float* gw = (const float*)d_in[1];   // [D,E]
    const float* w1 = (const float*)d_in[2];   // [E,D,H]
    const float* b1 = (const float*)d_in[3];   // [E,H]
    const float* w2 = (const float*)d_in[4];   // [E,H,D]
    const float* b2 = (const float*)d_in[5];   // [E,D]

    long s2 = in_sizes[2], s3 = in_sizes[3], s5 = in_sizes[5];
    int D = (int)(s2 / s3);       // E*D*H / (E*H)
    int E = (int)(s5 / D);
    int H = (int)(s3 / E);
    int N = (int)(in_sizes[0] / D);

    init_kernel<<<1, 32>>>(E);
    router_kernel<<<N, 128>>>(x, gw, D, E);
    scan_kernel<<<1, 32>>>(E);
    scatter_kernel<<<(N + 255) / 256, 256>>>(N);

    int MT = (2 * N + 127) / 128;   // worst-case M tiles per expert
    dim3 g1(H / 128, MT, E);
    gemm_kernel<1><<<g1, 256>>>(x, w1, b1, D, H);
    dim3 g2(D / 128, MT, E);
    gemm_kernel<2><<<g2, 256>>>(x, w2, b2, H, D);

    int Dq = D / 4;
    combine_kernel<<<(N * Dq + 255) / 256, 256>>>((float*)d_out, N, Dq);
}

// round 7
// speedup vs baseline: 1.4988x; 1.4988x over previous
#include <cuda_runtime.h>
#include <cuda_fp16.h>
#include <cstdint>
#include <math.h>

// MoE FFN: router top-2 -> grouped HMMA GEMM (in-kernel fp32->fp16 hi/lo split,
// 3-term mma.sync) -> combine. Pipeline structure identical to the passing R1
// kernel: no prep kernels, in-kernel gather, fp32 intermediates.

#define MAXE      16
#define CAP_ROWS  8192
#define CAP_H     4096
#define CAP_D     1024

__device__ int   g_cnt[MAXE];
__device__ int   g_off[MAXE];
__device__ int   g_cur[MAXE];
__device__ int   g_rows[CAP_ROWS];
__device__ int   g_tki[CAP_ROWS];
__device__ float g_tkw[CAP_ROWS];
__device__ float g_hidden[(size_t)CAP_ROWS * CAP_H];  // 128 MB
__device__ float g_ybuf[(size_t)CAP_ROWS * CAP_D];    // 32 MB

// ================================================================ mma helpers
__device__ __forceinline__ void mma16816(float* c, const uint32_t* a,
                                         const uint32_t* b) {
    asm volatile(
        "mma.sync.aligned.m16n8k16.row.col.f32.f16.f16.f32 "
        "{%0,%1,%2,%3}, {%4,%5,%6,%7}, {%8,%9}, {%0,%1,%2,%3};"
        : "+f"(c[0]), "+f"(c[1]), "+f"(c[2]), "+f"(c[3])
        : "r"(a[0]), "r"(a[1]), "r"(a[2]), "r"(a[3]), "r"(b[0]), "r"(b[1]));
}
__device__ __forceinline__ uint32_t packh(__half a, __half b) {
    return (uint32_t)__half_as_ushort(a) | ((uint32_t)__half_as_ushort(b) << 16);
}
__device__ __forceinline__ float gelu_exact(float v) {
    return 0.5f * v * (1.0f + erff(v * 0.70710678118654752f));
}

// ================================================================ router chain
__global__ void init_kernel(int E) {
    if (threadIdx.x < E) g_cnt[threadIdx.x] = 0;
}

__global__ __launch_bounds__(128) void router_kernel(
    const float* __restrict__ x, const float* __restrict__ gw, int D, int E)
{
    int n = blockIdx.x, t = threadIdx.x;
    float acc[MAXE];
    #pragma unroll
    for (int e = 0; e < MAXE; e++) acc[e] = 0.f;
    const float* xr = x + (size_t)n * D;
    for (int i = t; i < D; i += 128) {
        float xv = xr[i];
        const float* g = gw + (size_t)i * E;
        for (int e = 0; e < E; e++) acc[e] += xv * g[e];
    }
    for (int e = 0; e < E; e++)
        for (int o = 16; o > 0; o >>= 1)
            acc[e] += __shfl_down_sync(0xffffffffu, acc[e], o);
    __shared__ float sred[4][MAXE];
    int warp = t >> 5, lane = t & 31;
    if (lane == 0)
        for (int e = 0; e < E; e++) sred[warp][e] = acc[e];
    __syncthreads();
    if (t == 0) {
        float l[MAXE];
        for (int e = 0; e < E; e++)
            l[e] = sred[0][e] + sred[1][e] + sred[2][e] + sred[3][e];
        int i0 = 0;
        for (int e = 1; e < E; e++) if (l[e] > l[i0]) i0 = e;
        int i1 = -1;
        for (int e = 0; e < E; e++) {
            if (e == i0) continue;
            if (i1 < 0 || l[e] > l[i1]) i1 = e;
        }
        float e1 = expf(l[i1] - l[i0]);
        float s = 1.0f + e1;
        g_tki[n * 2 + 0] = i0;  g_tkw[n * 2 + 0] = 1.0f / s;
        g_tki[n * 2 + 1] = i1;  g_tkw[n * 2 + 1] = e1 / s;
        atomicAdd(&g_cnt[i0], 1);
        atomicAdd(&g_cnt[i1], 1);
    }
}

__global__ void scan_kernel(int E) {
    if (threadIdx.x == 0) {
        int off = 0;
        for (int e = 0; e < E; e++) { g_off[e] = off; g_cur[e] = off; off += g_cnt[e]; }
    }
}

__global__ void scatter_kernel(int N) {
    int n = blockIdx.x * blockDim.x + threadIdx.x;
    if (n >= N) return;
    #pragma unroll
    for (int k = 0; k < 2; k++) {
        int e = g_tki[n * 2 + k];
        int p = atomicAdd(&g_cur[e], 1);
        g_rows[p] = n * 2 + k;
    }
}

// ================================================================ HMMA grouped GEMM
// CTA tile 128x128, K-chunk 32. 8 warps (2x4), warp tile 64x32.
// SMEM: A as fp16 hi/lo [128][pitch 40 halves], B as fp32 [32][pitch 132 floats].
// Fragment reads proven conflict-free mod 32. Register double-buffer staging.
#define APITCH 40
#define BPITCH 132

template<int STAGE>
__global__ __launch_bounds__(256) void hmma_gemm(
    const float* __restrict__ Xin,     // x (stage1); unused stage2
    const float* __restrict__ Ball,    // w1 [E][D][H] or w2 [E][H][D] (native!)
    const float* __restrict__ biasAll, // [E][NC]
    int K, int NC)
{
    __shared__ __half sAh[128][APITCH];
    __shared__ __half sAl[128][APITCH];
    __shared__ float  sB[32][BPITCH];

    int e = blockIdx.z;
    int cnt = g_cnt[e];
    int m0 = blockIdx.y * 128;
    if (m0 >= cnt) return;
    int off = g_off[e];
    int n0 = blockIdx.x * 128;

    int tid = threadIdx.x, lane = tid & 31, wid = tid >> 5;
    int wm = wid >> 2, wn = wid & 3;          // 2 x 4 warp grid
    int gq = lane >> 2, tq = lane & 3;

    const float* Bb = Ball + (size_t)e * K * NC;   // rows k, cols n (native)

    // A staging: row = tid>>1, k-half = (tid&1)*16 floats (4 float4 each)
    int srow = tid >> 1, shalf = tid & 1;
    int arow0 = m0 + srow;
    int arcl = (arow0 < cnt) ? (off + arow0) : (off + cnt - 1);
    const float* arow;
    if (STAGE == 1) {
        int token = g_rows[arcl] >> 1;
        arow = Xin + (size_t)token * K;
    } else {
        arow = g_hidden + (size_t)arcl * K;
    }
    // B staging: k-row = tid>>3, n-col = (tid&7)*16 (4 float4 each)
    int brow = tid >> 3, bcol = (tid & 7) * 16;

    float4 rA[4], rB[4];
    auto ldreg = [&](int kc) {
        const float* ap = arow + kc * 32 + shalf * 16;
        const float* bp = Bb + (size_t)(kc * 32 + brow) * NC + n0 + bcol;
        #pragma unroll
        for (int q = 0; q < 4; q++) rA[q] = *(const float4*)(ap + q * 4);
        #pragma unroll
        for (int q = 0; q < 4; q++) rB[q] = *(const float4*)(bp + q * 4);
    };
    auto stsmem = [&]() {
        #pragma unroll
        for (int q = 0; q < 4; q++) {
            float4 v = rA[q];
            __half h0 = __float2half_rn(v.x), h1 = __float2half_rn(v.y);
            __half h2 = __float2half_rn(v.z), h3 = __float2half_rn(v.w);
            __half l0 = __float2half_rn(v.x - __half2float(h0));
            __half l1 = __float2half_rn(v.y - __half2float(h1));
            __half l2 = __float2half_rn(v.z - __half2float(h2));
            __half l3 = __float2half_rn(v.w - __half2float(h3));
            int c = shalf * 16 + q * 4;
            uint2 hp = make_uint2(packh(h0, h1), packh(h2, h3));
            uint2 lp = make_uint2(packh(l0, l1), packh(l2, l3));
            *(uint2*)&sAh[srow][c] = hp;
            *(uint2*)&sAl[srow][c] = lp;
            *(float4*)&sB[brow][bcol + q * 4] = rB[q];
        }
    };

    float acc[4][4][4];
    #pragma unroll
    for (int i = 0; i < 4; i++)
        #pragma unroll
        for (int j = 0; j < 4; j++)
            #pragma unroll
            for (int q = 0; q < 4; q++) acc[i][j][q] = 0.f;

    int KC = K / 32;
    ldreg(0);

    for (int kc = 0; kc < KC; kc++) {
        __syncthreads();   // prior chunk fully consumed
        stsmem();
        __syncthreads();
        if (kc + 1 < KC) ldreg(kc + 1);

        #pragma unroll
        for (int ks = 0; ks < 2; ks++) {
            int k0 = ks * 16 + tq * 2;
            uint32_t ah[4][4], al[4][4], bh[4][2], bl[4][2];
            #pragma unroll
            for (int mt = 0; mt < 4; mt++) {
                int r = wm * 64 + mt * 16 + gq;
                ah[mt][0] = *(const uint32_t*)&sAh[r][k0];
                ah[mt][1] = *(const uint32_t*)&sAh[r + 8][k0];
                ah[mt][2] = *(const uint32_t*)&sAh[r][k0 + 8];
                ah[mt][3] = *(const uint32_t*)&sAh[r + 8][k0 + 8];
                al[mt][0] = *(const uint32_t*)&sAl[r][k0];
                al[mt][1] = *(const uint32_t*)&sAl[r + 8][k0];
                al[mt][2] = *(const uint32_t*)&sAl[r][k0 + 8];
                al[mt][3] = *(const uint32_t*)&sAl[r + 8][k0 + 8];
            }
            #pragma unroll
            for (int nt = 0; nt < 4; nt++) {
                int n = wn * 32 + nt * 8 + gq;
                float x0 = sB[k0][n],     x1 = sB[k0 + 1][n];
                float x2 = sB[k0 + 8][n], x3 = sB[k0 + 9][n];
                __half p0 = __float2half_rn(x0), p1 = __float2half_rn(x1);
                __half p2 = __float2half_rn(x2), p3 = __float2half_rn(x3);
                bh[nt][0] = packh(p0, p1);
                bh[nt][1] = packh(p2, p3);
                bl[nt][0] = packh(__float2half_rn(x0 - __half2float(p0)),
                                  __float2half_rn(x1 - __half2float(p1)));
                bl[nt][1] = packh(__float2half_rn(x2 - __half2float(p2)),
                                  __float2half_rn(x3 - __half2float(p3)));
            }
            #pragma unroll
            for (int mt = 0; mt < 4; mt++)
                #pragma unroll
                for (int nt = 0; nt < 4; nt++) {
                    mma16816(acc[mt][nt], ah[mt], bh[nt]);
                    mma16816(acc[mt][nt], al[mt], bh[nt]);
                    mma16816(acc[mt][nt], ah[mt], bl[nt]);
                }
        }
    }

    // epilogue: rows wm*64+mt*16+gq(+8), cols wn*32+nt*8+tq*2
    const float* bias = biasAll + (size_t)e * NC + n0;
    #pragma unroll
    for (int mt = 0; mt < 4; mt++) {
        #pragma unroll
        for (int h = 0; h < 2; h++) {
            int mg = m0 + wm * 64 + mt * 16 + gq + h * 8;
            if (mg >= cnt) continue;
            size_t prow = (size_t)off + mg;
            int drow = (STAGE == 2) ? g_rows[prow] : 0;
            #pragma unroll
            for (int nt = 0; nt < 4; nt++) {
                int colL = wn * 32 + nt * 8 + tq * 2;
                float v0 = acc[mt][nt][h * 2 + 0] + bias[colL];
                float v1 = acc[mt][nt][h * 2 + 1] + bias[colL + 1];
                if (STAGE == 1) {
                    float2 o = make_float2(gelu_exact(v0), gelu_exact(v1));
                    *(float2*)(g_hidden + prow * NC + n0 + colL) = o;
                } else {
                    float2 o = make_float2(v0, v1);
                    *(float2*)(g_ybuf + (size_t)drow * NC + n0 + colL) = o;
                }
            }
        }
    }
}

// ================================================================ combine
__global__ void combine_kernel(float* __restrict__ out, int N, int Dq) {
    int id = blockIdx.x * blockDim.x + threadIdx.x;
    if (id >= N * Dq) return;
    int n = id / Dq, d4 = id % Dq;
    float w0 = g_tkw[n * 2 + 0];
    float w1 = g_tkw[n * 2 + 1];
    const float4* y0 = (const float4*)&g_ybuf[(size_t)(n * 2 + 0) * Dq * 4];
    const float4* y1 = (const float4*)&g_ybuf[(size_t)(n * 2 + 1) * Dq * 4];
    float4 a = y0[d4], b = y1[d4];
    float4 r;
    r.x = w0 * a.x + w1 * b.x;
    r.y = w0 * a.y + w1 * b.y;
    r.z = w0 * a.z + w1 * b.z;
    r.w = w0 * a.w + w1 * b.w;
    ((float4*)out)[id] = r;
}

// ================================================================ launch
extern "C" void kernel_launch(void* const* d_in, const int* in_sizes, int n_in,
                              void* d_out, int out_size) {
    const float* x  = (const float*)d_in[0];   // [B,T,D]
    const float* gw = (const float*)d_in[1];   // [D,E]
    const float* w1 = (const float*)d_in[2];   // [E,D,H]
    const float* b1 = (const float*)d_in[3];   // [E,H]
    const float* w2 = (const float*)d_in[4];   // [E,H,D]
    const float* b2 = (const float*)d_in[5];   // [E,D]

    long s2 = in_sizes[2], s3 = in_sizes[3], s5 = in_sizes[5];
    int D = (int)(s2 / s3);
    int E = (int)(s5 / D);
    int H = (int)(s3 / E);
    int N = (int)(in_sizes[0] / D);
    int N2 = 2 * N;

    init_kernel<<<1, 32>>>(E);
    router_kernel<<<N, 128>>>(x, gw, D, E);
    scan_kernel<<<1, 32>>>(E);
    scatter_kernel<<<(N + 255) / 256, 256>>>(N);

    int MT = (N2 + 127) / 128;
    dim3 g1(H / 128, MT, E);
    hmma_gemm<1><<<g1, 256>>>(x, w1, b1, D, H);
    dim3 g2(D / 128, MT, E);
    hmma_gemm<2><<<g2, 256>>>(x, w2, b2, H, D);

    int Dq = D / 4;
    combine_kernel<<<(N * Dq + 255) / 256, 256>>>((float*)d_out, N, Dq);
}

// round 8
// speedup vs baseline: 1.6327x; 1.0893x over previous
#include <cuda_runtime.h>
#include <cuda_fp16.h>
#include <cstdint>
#include <math.h>

// MoE FFN: router top-2 -> grouped HMMA GEMM (in-kernel fp32->fp16 hi/lo split,
// 3-term mma.sync) -> combine. R8: B split once at staging (k-pair packed),
// m-tile-innermost grid for B-tile L2 reuse.

#define MAXE      16
#define CAP_ROWS  8192
#define CAP_H     4096
#define CAP_D     1024

__device__ int   g_cnt[MAXE];
__device__ int   g_off[MAXE];
__device__ int   g_cur[MAXE];
__device__ int   g_rows[CAP_ROWS];
__device__ int   g_tki[CAP_ROWS];
__device__ float g_tkw[CAP_ROWS];
__device__ float g_hidden[(size_t)CAP_ROWS * CAP_H];  // 128 MB
__device__ float g_ybuf[(size_t)CAP_ROWS * CAP_D];    // 32 MB

// ================================================================ mma helpers
__device__ __forceinline__ void mma16816(float* c, const uint32_t* a,
                                         const uint32_t* b) {
    asm volatile(
        "mma.sync.aligned.m16n8k16.row.col.f32.f16.f16.f32 "
        "{%0,%1,%2,%3}, {%4,%5,%6,%7}, {%8,%9}, {%0,%1,%2,%3};"
        : "+f"(c[0]), "+f"(c[1]), "+f"(c[2]), "+f"(c[3])
        : "r"(a[0]), "r"(a[1]), "r"(a[2]), "r"(a[3]), "r"(b[0]), "r"(b[1]));
}
__device__ __forceinline__ uint32_t packh(__half a, __half b) {
    return (uint32_t)__half_as_ushort(a) | ((uint32_t)__half_as_ushort(b) << 16);
}
__device__ __forceinline__ float gelu_exact(float v) {
    return 0.5f * v * (1.0f + erff(v * 0.70710678118654752f));
}

// ================================================================ router chain
__global__ void init_kernel(int E) {
    if (threadIdx.x < E) g_cnt[threadIdx.x] = 0;
}

__global__ __launch_bounds__(128) void router_kernel(
    const float* __restrict__ x, const float* __restrict__ gw, int D, int E)
{
    int n = blockIdx.x, t = threadIdx.x;
    float acc[MAXE];
    #pragma unroll
    for (int e = 0; e < MAXE; e++) acc[e] = 0.f;
    const float* xr = x + (size_t)n * D;
    for (int i = t; i < D; i += 128) {
        float xv = xr[i];
        const float* g = gw + (size_t)i * E;
        for (int e = 0; e < E; e++) acc[e] += xv * g[e];
    }
    for (int e = 0; e < E; e++)
        for (int o = 16; o > 0; o >>= 1)
            acc[e] += __shfl_down_sync(0xffffffffu, acc[e], o);
    __shared__ float sred[4][MAXE];
    int warp = t >> 5, lane = t & 31;
    if (lane == 0)
        for (int e = 0; e < E; e++) sred[warp][e] = acc[e];
    __syncthreads();
    if (t == 0) {
        float l[MAXE];
        for (int e = 0; e < E; e++)
            l[e] = sred[0][e] + sred[1][e] + sred[2][e] + sred[3][e];
        int i0 = 0;
        for (int e = 1; e < E; e++) if (l[e] > l[i0]) i0 = e;
        int i1 = -1;
        for (int e = 0; e < E; e++) {
            if (e == i0) continue;
            if (i1 < 0 || l[e] > l[i1]) i1 = e;
        }
        float e1 = expf(l[i1] - l[i0]);
        float s = 1.0f + e1;
        g_tki[n * 2 + 0] = i0;  g_tkw[n * 2 + 0] = 1.0f / s;
        g_tki[n * 2 + 1] = i1;  g_tkw[n * 2 + 1] = e1 / s;
        atomicAdd(&g_cnt[i0], 1);
        atomicAdd(&g_cnt[i1], 1);
    }
}

__global__ void scan_kernel(int E) {
    if (threadIdx.x == 0) {
        int off = 0;
        for (int e = 0; e < E; e++) { g_off[e] = off; g_cur[e] = off; off += g_cnt[e]; }
    }
}

__global__ void scatter_kernel(int N) {
    int n = blockIdx.x * blockDim.x + threadIdx.x;
    if (n >= N) return;
    #pragma unroll
    for (int k = 0; k < 2; k++) {
        int e = g_tki[n * 2 + k];
        int p = atomicAdd(&g_cur[e], 1);
        g_rows[p] = n * 2 + k;
    }
}

// ================================================================ HMMA grouped GEMM
// CTA tile 128x128, K-chunk 32. 8 warps (2x4), warp tile 64x32.
// SMEM: A fp16 hi/lo [128][40 halves]; B k-pair packed uint32 [16][136].
// B split happens ONCE per element at staging. All fragment reads LDS.32,
// conflict-free (tq*8+gq covers 0..31 mod 32 with pitch 136).
#define APITCH 40
#define BPITCH 136

template<int STAGE>
__global__ __launch_bounds__(256) void hmma_gemm(
    const float* __restrict__ Xin,     // x (stage1); unused stage2
    const float* __restrict__ Ball,    // w1 [E][D][H] / w2 [E][H][D] (native)
    const float* __restrict__ biasAll, // [E][NC]
    int K, int NC)
{
    __shared__ __half    sAh[128][APITCH];
    __shared__ __half    sAl[128][APITCH];
    __shared__ uint32_t  sBh[16][BPITCH];
    __shared__ uint32_t  sBl[16][BPITCH];

    int e = blockIdx.z;
    int cnt = g_cnt[e];
    int m0 = blockIdx.x * 128;           // m-tile INNERMOST for B L2 reuse
    if (m0 >= cnt) return;
    int off = g_off[e];
    int n0 = blockIdx.y * 128;

    int tid = threadIdx.x, lane = tid & 31, wid = tid >> 5;
    int wm = wid >> 2, wn = wid & 3;      // 2 x 4 warp grid
    int gq = lane >> 2, tq = lane & 3;

    const float* Bb = Ball + (size_t)e * K * NC;

    // A staging: row = tid>>1, k-half = (tid&1)*16 floats
    int srow = tid >> 1, shalf = tid & 1;
    int arow0 = m0 + srow;
    int arcl = (arow0 < cnt) ? (off + arow0) : (off + cnt - 1);
    const float* arow;
    if (STAGE == 1) {
        int token = g_rows[arcl] >> 1;
        arow = Xin + (size_t)token * K;
    } else {
        arow = g_hidden + (size_t)arcl * K;
    }
    // B staging: kpair = tid>>4 (0..15), n8 = (tid&15)*8
    int bkp = tid >> 4, bn8 = (tid & 15) * 8;

    float4 rA[4], rB0[2], rB1[2];
    auto ldreg = [&](int kc) {
        const float* ap = arow + kc * 32 + shalf * 16;
        #pragma unroll
        for (int q = 0; q < 4; q++) rA[q] = *(const float4*)(ap + q * 4);
        const float* bp0 = Bb + (size_t)(kc * 32 + 2 * bkp) * NC + n0 + bn8;
        const float* bp1 = bp0 + NC;
        #pragma unroll
        for (int q = 0; q < 2; q++) {
            rB0[q] = *(const float4*)(bp0 + q * 4);
            rB1[q] = *(const float4*)(bp1 + q * 4);
        }
    };
    auto stsmem = [&]() {
        #pragma unroll
        for (int q = 0; q < 4; q++) {
            float4 v = rA[q];
            __half h0 = __float2half_rn(v.x), h1 = __float2half_rn(v.y);
            __half h2 = __float2half_rn(v.z), h3 = __float2half_rn(v.w);
            __half l0 = __float2half_rn(v.x - __half2float(h0));
            __half l1 = __float2half_rn(v.y - __half2float(h1));
            __half l2 = __float2half_rn(v.z - __half2float(h2));
            __half l3 = __float2half_rn(v.w - __half2float(h3));
            int c = shalf * 16 + q * 4;
            *(uint2*)&sAh[srow][c] = make_uint2(packh(h0, h1), packh(h2, h3));
            *(uint2*)&sAl[srow][c] = make_uint2(packh(l0, l1), packh(l2, l3));
        }
        // B: pack halves (k, k+1) per n into one uint32
        uint32_t bh[8], bl[8];
        const float* f0 = (const float*)rB0;
        const float* f1 = (const float*)rB1;
        #pragma unroll
        for (int j = 0; j < 8; j++) {
            float a = f0[j], b = f1[j];
            __half ha = __float2half_rn(a), hb = __float2half_rn(b);
            bh[j] = packh(ha, hb);
            bl[j] = packh(__float2half_rn(a - __half2float(ha)),
                          __float2half_rn(b - __half2float(hb)));
        }
        *(uint4*)&sBh[bkp][bn8]     = *(uint4*)&bh[0];
        *(uint4*)&sBh[bkp][bn8 + 4] = *(uint4*)&bh[4];
        *(uint4*)&sBl[bkp][bn8]     = *(uint4*)&bl[0];
        *(uint4*)&sBl[bkp][bn8 + 4] = *(uint4*)&bl[4];
    };

    float acc[4][4][4];
    #pragma unroll
    for (int i = 0; i < 4; i++)
        #pragma unroll
        for (int j = 0; j < 4; j++)
            #pragma unroll
            for (int q = 0; q < 4; q++) acc[i][j][q] = 0.f;

    int KC = K / 32;
    ldreg(0);

    for (int kc = 0; kc < KC; kc++) {
        __syncthreads();   // prior chunk fully consumed
        stsmem();
        __syncthreads();
        if (kc + 1 < KC) ldreg(kc + 1);

        #pragma unroll
        for (int ks = 0; ks < 2; ks++) {
            int k0 = ks * 16 + tq * 2;
            int kp = ks * 8 + tq;
            uint32_t ah[4][4], al[4][4], bh[4][2], bl[4][2];
            #pragma unroll
            for (int mt = 0; mt < 4; mt++) {
                int r = wm * 64 + mt * 16 + gq;
                ah[mt][0] = *(const uint32_t*)&sAh[r][k0];
                ah[mt][1] = *(const uint32_t*)&sAh[r + 8][k0];
                ah[mt][2] = *(const uint32_t*)&sAh[r][k0 + 8];
                ah[mt][3] = *(const uint32_t*)&sAh[r + 8][k0 + 8];
                al[mt][0] = *(const uint32_t*)&sAl[r][k0];
                al[mt][1] = *(const uint32_t*)&sAl[r + 8][k0];
                al[mt][2] = *(const uint32_t*)&sAl[r][k0 + 8];
                al[mt][3] = *(const uint32_t*)&sAl[r + 8][k0 + 8];
            }
            #pragma unroll
            for (int nt = 0; nt < 4; nt++) {
                int n = wn * 32 + nt * 8 + gq;
                bh[nt][0] = sBh[kp][n];
                bh[nt][1] = sBh[kp + 4][n];
                bl[nt][0] = sBl[kp][n];
                bl[nt][1] = sBl[kp + 4][n];
            }
            #pragma unroll
            for (int mt = 0; mt < 4; mt++)
                #pragma unroll
                for (int nt = 0; nt < 4; nt++) {
                    mma16816(acc[mt][nt], ah[mt], bh[nt]);
                    mma16816(acc[mt][nt], al[mt], bh[nt]);
                    mma16816(acc[mt][nt], ah[mt], bl[nt]);
                }
        }
    }

    // epilogue: rows wm*64+mt*16+gq(+8), cols wn*32+nt*8+tq*2
    const float* bias = biasAll + (size_t)e * NC + n0;
    #pragma unroll
    for (int mt = 0; mt < 4; mt++) {
        #pragma unroll
        for (int h = 0; h < 2; h++) {
            int mg = m0 + wm * 64 + mt * 16 + gq + h * 8;
            if (mg >= cnt) continue;
            size_t prow = (size_t)off + mg;
            int drow = (STAGE == 2) ? g_rows[prow] : 0;
            #pragma unroll
            for (int nt = 0; nt < 4; nt++) {
                int colL = wn * 32 + nt * 8 + tq * 2;
                float v0 = acc[mt][nt][h * 2 + 0] + bias[colL];
                float v1 = acc[mt][nt][h * 2 + 1] + bias[colL + 1];
                if (STAGE == 1) {
                    float2 o = make_float2(gelu_exact(v0), gelu_exact(v1));
                    *(float2*)(g_hidden + prow * NC + n0 + colL) = o;
                } else {
                    float2 o = make_float2(v0, v1);
                    *(float2*)(g_ybuf + (size_t)drow * NC + n0 + colL) = o;
                }
            }
        }
    }
}

// ================================================================ combine
__global__ void combine_kernel(float* __restrict__ out, int N, int Dq) {
    int id = blockIdx.x * blockDim.x + threadIdx.x;
    if (id >= N * Dq) return;
    int n = id / Dq, d4 = id % Dq;
    float w0 = g_tkw[n * 2 + 0];
    float w1 = g_tkw[n * 2 + 1];
    const float4* y0 = (const float4*)&g_ybuf[(size_t)(n * 2 + 0) * Dq * 4];
    const float4* y1 = (const float4*)&g_ybuf[(size_t)(n * 2 + 1) * Dq * 4];
    float4 a = y0[d4], b = y1[d4];
    float4 r;
    r.x = w0 * a.x + w1 * b.x;
    r.y = w0 * a.y + w1 * b.y;
    r.z = w0 * a.z + w1 * b.z;
    r.w = w0 * a.w + w1 * b.w;
    ((float4*)out)[id] = r;
}

// ================================================================ launch
extern "C" void kernel_launch(void* const* d_in, const int* in_sizes, int n_in,
                              void* d_out, int out_size) {
    const float* x  = (const float*)d_in[0];   // [B,T,D]
    const float* gw = (const float*)d_in[1];   // [D,E]
    const float* w1 = (const float*)d_in[2];   // [E,D,H]
    const float* b1 = (const float*)d_in[3];   // [E,H]
    const float* w2 = (const float*)d_in[4];   // [E,H,D]
    const float* b2 = (const float*)d_in[5];   // [E,D]

    long s2 = in_sizes[2], s3 = in_sizes[3], s5 = in_sizes[5];
    int D = (int)(s2 / s3);
    int E = (int)(s5 / D);
    int H = (int)(s3 / E);
    int N = (int)(in_sizes[0] / D);
    int N2 = 2 * N;

    init_kernel<<<1, 32>>>(E);
    router_kernel<<<N, 128>>>(x, gw, D, E);
    scan_kernel<<<1, 32>>>(E);
    scatter_kernel<<<(N + 255) / 256, 256>>>(N);

    int MT = (N2 + 127) / 128;
    dim3 g1(MT, H / 128, E);               // m-tile innermost
    hmma_gemm<1><<<g1, 256>>>(x, w1, b1, D, H);
    dim3 g2(MT, D / 128, E);
    hmma_gemm<2><<<g2, 256>>>(x, w2, b2, H, D);

    int Dq = D / 4;
    combine_kernel<<<(N * Dq + 255) / 256, 256>>>((float*)d_out, N, Dq);
}

// round 9
// speedup vs baseline: 2.6070x; 1.5967x over previous
#include <cuda_runtime.h>
#include <cuda_fp16.h>
#include <cstdint>
#include <math.h>

// MoE FFN: router top-2 -> grouped HMMA GEMM (in-kernel fp32->fp16 hi/lo split,
// 2-term mma.sync: Ah*Bh + Al*Bh) -> combine. R9: dropped Ah*Bl term, 2 CTAs/SM.

#define MAXE      16
#define CAP_ROWS  8192
#define CAP_H     4096
#define CAP_D     1024

__device__ int   g_cnt[MAXE];
__device__ int   g_off[MAXE];
__device__ int   g_cur[MAXE];
__device__ int   g_rows[CAP_ROWS];
__device__ int   g_tki[CAP_ROWS];
__device__ float g_tkw[CAP_ROWS];
__device__ float g_hidden[(size_t)CAP_ROWS * CAP_H];  // 128 MB
__device__ float g_ybuf[(size_t)CAP_ROWS * CAP_D];    // 32 MB

// ================================================================ mma helpers
__device__ __forceinline__ void mma16816(float* c, const uint32_t* a,
                                         const uint32_t* b) {
    asm volatile(
        "mma.sync.aligned.m16n8k16.row.col.f32.f16.f16.f32 "
        "{%0,%1,%2,%3}, {%4,%5,%6,%7}, {%8,%9}, {%0,%1,%2,%3};"
        : "+f"(c[0]), "+f"(c[1]), "+f"(c[2]), "+f"(c[3])
        : "r"(a[0]), "r"(a[1]), "r"(a[2]), "r"(a[3]), "r"(b[0]), "r"(b[1]));
}
__device__ __forceinline__ uint32_t packh(__half a, __half b) {
    return (uint32_t)__half_as_ushort(a) | ((uint32_t)__half_as_ushort(b) << 16);
}
__device__ __forceinline__ float gelu_exact(float v) {
    return 0.5f * v * (1.0f + erff(v * 0.70710678118654752f));
}

// ================================================================ router chain
__global__ void init_kernel(int E) {
    if (threadIdx.x < E) g_cnt[threadIdx.x] = 0;
}

__global__ __launch_bounds__(128) void router_kernel(
    const float* __restrict__ x, const float* __restrict__ gw, int D, int E)
{
    int n = blockIdx.x, t = threadIdx.x;
    float acc[MAXE];
    #pragma unroll
    for (int e = 0; e < MAXE; e++) acc[e] = 0.f;
    const float* xr = x + (size_t)n * D;
    for (int i = t; i < D; i += 128) {
        float xv = xr[i];
        const float* g = gw + (size_t)i * E;
        for (int e = 0; e < E; e++) acc[e] += xv * g[e];
    }
    for (int e = 0; e < E; e++)
        for (int o = 16; o > 0; o >>= 1)
            acc[e] += __shfl_down_sync(0xffffffffu, acc[e], o);
    __shared__ float sred[4][MAXE];
    int warp = t >> 5, lane = t & 31;
    if (lane == 0)
        for (int e = 0; e < E; e++) sred[warp][e] = acc[e];
    __syncthreads();
    if (t == 0) {
        float l[MAXE];
        for (int e = 0; e < E; e++)
            l[e] = sred[0][e] + sred[1][e] + sred[2][e] + sred[3][e];
        int i0 = 0;
        for (int e = 1; e < E; e++) if (l[e] > l[i0]) i0 = e;
        int i1 = -1;
        for (int e = 0; e < E; e++) {
            if (e == i0) continue;
            if (i1 < 0 || l[e] > l[i1]) i1 = e;
        }
        float e1 = expf(l[i1] - l[i0]);
        float s = 1.0f + e1;
        g_tki[n * 2 + 0] = i0;  g_tkw[n * 2 + 0] = 1.0f / s;
        g_tki[n * 2 + 1] = i1;  g_tkw[n * 2 + 1] = e1 / s;
        atomicAdd(&g_cnt[i0], 1);
        atomicAdd(&g_cnt[i1], 1);
    }
}

__global__ void scan_kernel(int E) {
    if (threadIdx.x == 0) {
        int off = 0;
        for (int e = 0; e < E; e++) { g_off[e] = off; g_cur[e] = off; off += g_cnt[e]; }
    }
}

__global__ void scatter_kernel(int N) {
    int n = blockIdx.x * blockDim.x + threadIdx.x;
    if (n >= N) return;
    #pragma unroll
    for (int k = 0; k < 2; k++) {
        int e = g_tki[n * 2 + k];
        int p = atomicAdd(&g_cur[e], 1);
        g_rows[p] = n * 2 + k;
    }
}

// ================================================================ HMMA grouped GEMM
// CTA tile 128x128, K-chunk 32. 8 warps (2x4), warp tile 64x32.
// SMEM: A fp16 hi/lo [128][40]; B hi-only k-pair packed uint32 [16][136].
// 2-term split: acc = Ah*Bh + Al*Bh. Reg budget <=128 (2 CTAs/SM):
// A-fragments loaded per-mt to shrink live range.
#define APITCH 40
#define BPITCH 136

template<int STAGE>
__global__ __launch_bounds__(256, 2) void hmma_gemm(
    const float* __restrict__ Xin,     // x (stage1); unused stage2
    const float* __restrict__ Ball,    // w1 [E][D][H] / w2 [E][H][D] (native)
    const float* __restrict__ biasAll, // [E][NC]
    int K, int NC)
{
    __shared__ __half    sAh[128][APITCH];
    __shared__ __half    sAl[128][APITCH];
    __shared__ uint32_t  sBh[16][BPITCH];

    int e = blockIdx.z;
    int cnt = g_cnt[e];
    int m0 = blockIdx.x * 128;           // m-tile innermost: B L2 reuse
    if (m0 >= cnt) return;
    int off = g_off[e];
    int n0 = blockIdx.y * 128;

    int tid = threadIdx.x, lane = tid & 31, wid = tid >> 5;
    int wm = wid >> 2, wn = wid & 3;      // 2 x 4 warp grid
    int gq = lane >> 2, tq = lane & 3;

    const float* Bb = Ball + (size_t)e * K * NC;

    // A staging: row = tid>>1, k-half = (tid&1)*16 floats
    int srow = tid >> 1, shalf = tid & 1;
    int arow0 = m0 + srow;
    int arcl = (arow0 < cnt) ? (off + arow0) : (off + cnt - 1);
    const float* arow;
    if (STAGE == 1) {
        int token = g_rows[arcl] >> 1;
        arow = Xin + (size_t)token * K;
    } else {
        arow = g_hidden + (size_t)arcl * K;
    }
    // B staging: kpair = tid>>4 (0..15), n8 = (tid&15)*8
    int bkp = tid >> 4, bn8 = (tid & 15) * 8;

    float4 rA[4];
    auto ldregA = [&](int kc) {
        const float* ap = arow + kc * 32 + shalf * 16;
        #pragma unroll
        for (int q = 0; q < 4; q++) rA[q] = *(const float4*)(ap + q * 4);
    };
    auto stsmem = [&](int kc) {
        #pragma unroll
        for (int q = 0; q < 4; q++) {
            float4 v = rA[q];
            __half h0 = __float2half_rn(v.x), h1 = __float2half_rn(v.y);
            __half h2 = __float2half_rn(v.z), h3 = __float2half_rn(v.w);
            __half l0 = __float2half_rn(v.x - __half2float(h0));
            __half l1 = __float2half_rn(v.y - __half2float(h1));
            __half l2 = __float2half_rn(v.z - __half2float(h2));
            __half l3 = __float2half_rn(v.w - __half2float(h3));
            int c = shalf * 16 + q * 4;
            *(uint2*)&sAh[srow][c] = make_uint2(packh(h0, h1), packh(h2, h3));
            *(uint2*)&sAl[srow][c] = make_uint2(packh(l0, l1), packh(l2, l3));
        }
        // B hi only: pack halves (k, k+1) per n into one uint32
        const float* bp0 = Bb + (size_t)(kc * 32 + 2 * bkp) * NC + n0 + bn8;
        const float* bp1 = bp0 + NC;
        #pragma unroll
        for (int q = 0; q < 2; q++) {
            float4 a4 = *(const float4*)(bp0 + q * 4);
            float4 b4 = *(const float4*)(bp1 + q * 4);
            uint4 o;
            o.x = packh(__float2half_rn(a4.x), __float2half_rn(b4.x));
            o.y = packh(__float2half_rn(a4.y), __float2half_rn(b4.y));
            o.z = packh(__float2half_rn(a4.z), __float2half_rn(b4.z));
            o.w = packh(__float2half_rn(a4.w), __float2half_rn(b4.w));
            *(uint4*)&sBh[bkp][bn8 + q * 4] = o;
        }
    };

    float acc[4][4][4];
    #pragma unroll
    for (int i = 0; i < 4; i++)
        #pragma unroll
        for (int j = 0; j < 4; j++)
            #pragma unroll
            for (int q = 0; q < 4; q++) acc[i][j][q] = 0.f;

    int KC = K / 32;
    ldregA(0);

    for (int kc = 0; kc < KC; kc++) {
        __syncthreads();   // prior chunk consumed
        stsmem(kc);
        __syncthreads();
        if (kc + 1 < KC) ldregA(kc + 1);

        #pragma unroll
        for (int ks = 0; ks < 2; ks++) {
            int k0 = ks * 16 + tq * 2;
            int kp = ks * 8 + tq;
            uint32_t bh[4][2];
            #pragma unroll
            for (int nt = 0; nt < 4; nt++) {
                int n = wn * 32 + nt * 8 + gq;
                bh[nt][0] = sBh[kp][n];
                bh[nt][1] = sBh[kp + 4][n];
            }
            #pragma unroll
            for (int mt = 0; mt < 4; mt++) {
                int r = wm * 64 + mt * 16 + gq;
                uint32_t ah[4], al[4];
                ah[0] = *(const uint32_t*)&sAh[r][k0];
                ah[1] = *(const uint32_t*)&sAh[r + 8][k0];
                ah[2] = *(const uint32_t*)&sAh[r][k0 + 8];
                ah[3] = *(const uint32_t*)&sAh[r + 8][k0 + 8];
                al[0] = *(const uint32_t*)&sAl[r][k0];
                al[1] = *(const uint32_t*)&sAl[r + 8][k0];
                al[2] = *(const uint32_t*)&sAl[r][k0 + 8];
                al[3] = *(const uint32_t*)&sAl[r + 8][k0 + 8];
                #pragma unroll
                for (int nt = 0; nt < 4; nt++) {
                    mma16816(acc[mt][nt], ah, bh[nt]);
                    mma16816(acc[mt][nt], al, bh[nt]);
                }
            }
        }
    }

    // epilogue: rows wm*64+mt*16+gq(+8), cols wn*32+nt*8+tq*2
    const float* bias = biasAll + (size_t)e * NC + n0;
    #pragma unroll
    for (int mt = 0; mt < 4; mt++) {
        #pragma unroll
        for (int h = 0; h < 2; h++) {
            int mg = m0 + wm * 64 + mt * 16 + gq + h * 8;
            if (mg >= cnt) continue;
            size_t prow = (size_t)off + mg;
            int drow = (STAGE == 2) ? g_rows[prow] : 0;
            #pragma unroll
            for (int nt = 0; nt < 4; nt++) {
                int colL = wn * 32 + nt * 8 + tq * 2;
                float v0 = acc[mt][nt][h * 2 + 0] + bias[colL];
                float v1 = acc[mt][nt][h * 2 + 1] + bias[colL + 1];
                if (STAGE == 1) {
                    float2 o = make_float2(gelu_exact(v0), gelu_exact(v1));
                    *(float2*)(g_hidden + prow * NC + n0 + colL) = o;
                } else {
                    float2 o = make_float2(v0, v1);
                    *(float2*)(g_ybuf + (size_t)drow * NC + n0 + colL) = o;
                }
            }
        }
    }
}

// ================================================================ combine
__global__ void combine_kernel(float* __restrict__ out, int N, int Dq) {
    int id = blockIdx.x * blockDim.x + threadIdx.x;
    if (id >= N * Dq) return;
    int n = id / Dq, d4 = id % Dq;
    float w0 = g_tkw[n * 2 + 0];
    float w1 = g_tkw[n * 2 + 1];
    const float4* y0 = (const float4*)&g_ybuf[(size_t)(n * 2 + 0) * Dq * 4];
    const float4* y1 = (const float4*)&g_ybuf[(size_t)(n * 2 + 1) * Dq * 4];
    float4 a = y0[d4], b = y1[d4];
    float4 r;
    r.x = w0 * a.x + w1 * b.x;
    r.y = w0 * a.y + w1 * b.y;
    r.z = w0 * a.z + w1 * b.z;
    r.w = w0 * a.w + w1 * b.w;
    ((float4*)out)[id] = r;
}

// ================================================================ launch
extern "C" void kernel_launch(void* const* d_in, const int* in_sizes, int n_in,
                              void* d_out, int out_size) {
    const float* x  = (const float*)d_in[0];   // [B,T,D]
    const float* gw = (const float*)d_in[1];   // [D,E]
    const float* w1 = (const float*)d_in[2];   // [E,D,H]
    const float* b1 = (const float*)d_in[3];   // [E,H]
    const float* w2 = (const float*)d_in[4];   // [E,H,D]
    const float* b2 = (const float*)d_in[5];   // [E,D]

    long s2 = in_sizes[2], s3 = in_sizes[3], s5 = in_sizes[5];
    int D = (int)(s2 / s3);
    int E = (int)(s5 / D);
    int H = (int)(s3 / E);
    int N = (int)(in_sizes[0] / D);
    int N2 = 2 * N;

    init_kernel<<<1, 32>>>(E);
    router_kernel<<<N, 128>>>(x, gw, D, E);
    scan_kernel<<<1, 32>>>(E);
    scatter_kernel<<<(N + 255) / 256, 256>>>(N);

    int MT = (N2 + 127) / 128;
    dim3 g1(MT, H / 128, E);               // m-tile innermost
    hmma_gemm<1><<<g1, 256>>>(x, w1, b1, D, H);
    dim3 g2(MT, D / 128, E);
    hmma_gemm<2><<<g2, 256>>>(x, w2, b2, H, D);

    int Dq = D / 4;
    combine_kernel<<<(N * Dq + 255) / 256, 256>>>((float*)d_out, N, Dq);
}